// round 13
// baseline (speedup 1.0000x reference)
#include <cuda_runtime.h>
#include <cstdint>

#define WPB 8          // warps per block (4 pairs)
#define EPW 4          // elements per warp
#define NTHREADS 256
#define D 64
#define NS 8

typedef unsigned long long ull;

__device__ __forceinline__ ull pack2(float x, float y){
    ull r;
    asm("mov.b64 %0, {%1, %2};" : "=l"(r)
        : "r"(__float_as_uint(x)), "r"(__float_as_uint(y)));
    return r;
}
__device__ __forceinline__ void unpack2(ull p, float &x, float &y){
    unsigned int lo, hi;
    asm("mov.b64 {%0, %1}, %2;" : "=r"(lo), "=r"(hi) : "l"(p));
    x = __uint_as_float(lo); y = __uint_as_float(hi);
}
// packed fp32x2 ops (Blackwell)
__device__ __forceinline__ void ffma2(ull &acc, ull a, ull b){
    asm("fma.rn.f32x2 %0, %1, %2, %3;" : "=l"(acc) : "l"(a), "l"(b), "l"(acc));
}
__device__ __forceinline__ ull add2(ull a, ull b){
    ull r; asm("add.rn.f32x2 %0, %1, %2;" : "=l"(r) : "l"(a), "l"(b));
    return r;
}

// softmax over 8-lane group (lanes 8g..8g+7), one value per lane
__device__ __forceinline__ float gsoftmax8(float x){
    float m = x;
    m = fmaxf(m, __shfl_xor_sync(0xffffffffu, m, 1));
    m = fmaxf(m, __shfl_xor_sync(0xffffffffu, m, 2));
    m = fmaxf(m, __shfl_xor_sync(0xffffffffu, m, 4));
    float e = __expf(x - m);
    float sm = e;
    sm += __shfl_xor_sync(0xffffffffu, sm, 1);
    sm += __shfl_xor_sync(0xffffffffu, sm, 2);
    sm += __shfl_xor_sync(0xffffffffu, sm, 4);
    return e / sm;
}

// 8-element matvec: ONE matrix, x vectors from two warps' staging regions
// (xA = this pair's even-warp slots, xB = odd-warp slots). x read as plain
// floats via LDS.128; pair-duplication via ALU movs. relu applied.
__device__ __forceinline__ void matvec8(const ull* __restrict__ Wg,
                                        const ull* __restrict__ bg,
                                        const float* __restrict__ xA,
                                        const float* __restrict__ xB,
                                        ull* h, int lane){
    ull bias = bg[lane];
    ull acc[8];
    #pragma unroll
    for (int e = 0; e < 8; e++) acc[e] = bias;
    #pragma unroll 2
    for (int dq = 0; dq < D/4; dq++){
        ull w0 = Wg[(4*dq)  * 32 + lane];
        ull w1 = Wg[(4*dq+1)* 32 + lane];
        ull w2 = Wg[(4*dq+2)* 32 + lane];
        ull w3 = Wg[(4*dq+3)* 32 + lane];
        #pragma unroll
        for (int e = 0; e < 8; e++){
            const float* src = (e < 4) ? (xA + e*D) : (xB + (e-4)*D);
            float4 x4 = *(const float4*)(src + 4*dq);      // 4 dims / 1 wavefront
            ffma2(acc[e], w0, pack2(x4.x, x4.x));
            ffma2(acc[e], w1, pack2(x4.y, x4.y));
            ffma2(acc[e], w2, pack2(x4.z, x4.z));
            ffma2(acc[e], w3, pack2(x4.w, x4.w));
        }
    }
    #pragma unroll
    for (int e = 0; e < 8; e++){
        float a, b; unpack2(acc[e], a, b);
        h[e] = pack2(fmaxf(a, 0.f), fmaxf(b, 0.f));
    }
}

__global__ void __launch_bounds__(NTHREADS, 5)
sestkgcn_kernel(
    const int* __restrict__ u, const int* __restrict__ v,
    const float* __restrict__ usr_feat, const float* __restrict__ item_feat,
    const float* __restrict__ rel_feat,
    const int* __restrict__ neigh_uu, const float* __restrict__ uu_st,
    const int* __restrict__ neigh_ui, const float* __restrict__ ui_rat,
    const float* __restrict__ ui_vot, const float* __restrict__ ui_tim,
    const int* __restrict__ neigh_iu, const float* __restrict__ iu_rat,
    const float* __restrict__ iu_vot, const float* __restrict__ iu_tim,
    const int* __restrict__ neigh_ii, const int* __restrict__ neigh_ir,
    const float* __restrict__ Wu, const float* __restrict__ bu,
    const float* __restrict__ Wv, const float* __restrict__ bv,
    float* __restrict__ out, int batch)
{
    // plain x vectors: user slots 0..3, item slots 4..7 per warp: 16 KB
    __shared__ __align__(16) float sx[WPB][2*EPW][D];

    const int warp = threadIdx.x >> 5;
    const int lane = threadIdx.x & 31;
    const int base = (blockIdx.x * WPB + warp) * EPW;
    const int pair = warp >> 1;          // 0..3
    const int isodd = warp & 1;
    const int bar_id = 1 + pair;         // named barrier per pair

    const float4* usr4  = (const float4*)usr_feat;   // quarter base = id*16 + c
    const float4* item4 = (const float4*)item_feat;
    const float4* rel4  = (const float4*)rel_feat;

    const int h = lane >> 4;   // row-of-pair selector
    const int c = lane & 15;   // float4 dim-quarter

    // ---------- lane-parallel weights & indices: lane = (e = lane>>3, s = lane&7) ----------
    const int eg = lane >> 3, sg = lane & 7;
    int bb = base + eg; if (bb >= batch) bb = batch - 1;
    const int myu = __ldcg(u + bb);
    const int myv = __ldcg(v + bb);

    float w_uu = __ldcg(uu_st + myu*NS + sg);
    int   i_uu = __ldcg(neigh_uu + myu*NS + sg);
    float w_ui = __ldcg(ui_rat + myu*NS + sg) * __ldcg(ui_vot + myu*NS + sg)
               * __ldcg(ui_tim + myu*NS + sg);
    int   i_ui = __ldcg(neigh_ui + myu*NS + sg);
    float w_iu = __ldcg(iu_rat + myv*NS + sg) * __ldcg(iu_vot + myv*NS + sg)
               * __ldcg(iu_tim + myv*NS + sg);
    int   i_iu = __ldcg(neigh_iu + myv*NS + sg);
    int   i_ii = __ldcg(neigh_ii + myv*NS + sg);
    int   i_ir = __ldcg(neigh_ir + myv*NS + sg);

    w_uu = gsoftmax8(w_uu);
    w_ui = gsoftmax8(w_ui);
    w_iu = gsoftmax8(w_iu);

    const ull p_uu = pack2(w_uu, __int_as_float(i_uu));
    const ull p_ui = pack2(w_ui, __int_as_float(i_ui));
    const ull p_iu = pack2(w_iu, __int_as_float(i_iu));
    const ull p_ii = pack2(__int_as_float(i_ii), __int_as_float(i_ir));

    // =============== user side: paired-row gathers (stage to slots 0..3) ===============
    #pragma unroll
    for (int e = 0; e < EPW; e++){
        float ax = 0.f, ay = 0.f, az = 0.f, aw = 0.f;

        #pragma unroll
        for (int s = 0; s < 4; s++){
            ull t = __shfl_sync(0xffffffffu, p_uu, (e << 3) + 2*s + h);
            float wf, idf; unpack2(t, wf, idf);
            float4 f = __ldcg(usr4 + (size_t)__float_as_int(idf)*16 + c);
            ax = fmaf(wf, f.x, ax); ay = fmaf(wf, f.y, ay);
            az = fmaf(wf, f.z, az); aw = fmaf(wf, f.w, aw);
        }
        #pragma unroll
        for (int s = 0; s < 4; s++){
            ull t = __shfl_sync(0xffffffffu, p_ui, (e << 3) + 2*s + h);
            float wf, idf; unpack2(t, wf, idf);
            float4 f = __ldcg(item4 + (size_t)__float_as_int(idf)*16 + c);
            ax = fmaf(wf, f.x, ax); ay = fmaf(wf, f.y, ay);
            az = fmaf(wf, f.z, az); aw = fmaf(wf, f.w, aw);
        }
        ull qa = pack2(ax, ay), qb = pack2(az, aw);
        qa = add2(qa, __shfl_xor_sync(0xffffffffu, qa, 16));
        qb = add2(qb, __shfl_xor_sync(0xffffffffu, qb, 16));
        unpack2(qa, ax, ay); unpack2(qb, az, aw);
        int uid = __shfl_sync(0xffffffffu, myu, e << 3);
        float4 ub = __ldcg(usr4 + (size_t)uid*16 + c);
        ax += ub.x; ay += ub.y; az += ub.z; aw += ub.w;

        if (h == 0)
            *(float4*)(&sx[warp][e][4*c]) = make_float4(ax, ay, az, aw);
    }

    // =============== item side: paired-row gathers (stage to slots 4..7) ===============
    #pragma unroll
    for (int e = 0; e < EPW; e++){
        float ax = 0.f, ay = 0.f, az = 0.f, aw = 0.f;

        #pragma unroll
        for (int s = 0; s < 4; s++){
            ull t = __shfl_sync(0xffffffffu, p_iu, (e << 3) + 2*s + h);
            float wf, idf; unpack2(t, wf, idf);
            float4 f = __ldcg(usr4 + (size_t)__float_as_int(idf)*16 + c);
            ax = fmaf(wf, f.x, ax); ay = fmaf(wf, f.y, ay);
            az = fmaf(wf, f.z, az); aw = fmaf(wf, f.w, aw);
        }
        // KG neighbors with user-relation attention (paired rows, 16-lane reduce)
        {
            int uid = __shfl_sync(0xffffffffu, myu, e << 3);
            float4 ue = __ldcg(usr4 + (size_t)uid*16 + c);

            int iidx[4]; float4 fi[4]; float ps[4];
            #pragma unroll
            for (int s = 0; s < 4; s++){
                ull t = __shfl_sync(0xffffffffu, p_ii, (e << 3) + 2*s + h);
                float af, bf; unpack2(t, af, bf);
                iidx[s] = __float_as_int(af);
                fi[s] = __ldcg(item4 + (size_t)iidx[s]*16 + c);
                float4 rf = __ldcg(rel4 + (size_t)__float_as_int(bf)*16 + c);
                ps[s] = fmaf(ue.x, rf.x, fmaf(ue.y, rf.y, fmaf(ue.z, rf.z, ue.w * rf.w)));
            }
            ull q0 = pack2(ps[0], ps[1]), q1 = pack2(ps[2], ps[3]);
            #pragma unroll
            for (int o = 8; o; o >>= 1){
                q0 = add2(q0, __shfl_xor_sync(0xffffffffu, q0, o));
                q1 = add2(q1, __shfl_xor_sync(0xffffffffu, q1, o));
            }
            ull q0o = __shfl_xor_sync(0xffffffffu, q0, 16);
            ull q1o = __shfl_xor_sync(0xffffffffu, q1, 16);
            float d0,d1,d2,d3, o0,o1,o2,o3;
            unpack2(q0, d0, d1); unpack2(q1, d2, d3);
            unpack2(q0o, o0, o1); unpack2(q1o, o2, o3);
            float m = fmaxf(fmaxf(fmaxf(d0,d1), fmaxf(d2,d3)),
                            fmaxf(fmaxf(o0,o1), fmaxf(o2,o3)));
            float e0 = __expf(d0-m), e1 = __expf(d1-m), e2 = __expf(d2-m), e3 = __expf(d3-m);
            float sum = e0+e1+e2+e3 + __expf(o0-m)+__expf(o1-m)+__expf(o2-m)+__expf(o3-m);
            float inv = 1.f / sum;
            ax = fmaf(e0*inv, fi[0].x, ax); ay = fmaf(e0*inv, fi[0].y, ay);
            az = fmaf(e0*inv, fi[0].z, az); aw = fmaf(e0*inv, fi[0].w, aw);
            ax = fmaf(e1*inv, fi[1].x, ax); ay = fmaf(e1*inv, fi[1].y, ay);
            az = fmaf(e1*inv, fi[1].z, az); aw = fmaf(e1*inv, fi[1].w, aw);
            ax = fmaf(e2*inv, fi[2].x, ax); ay = fmaf(e2*inv, fi[2].y, ay);
            az = fmaf(e2*inv, fi[2].z, az); aw = fmaf(e2*inv, fi[2].w, aw);
            ax = fmaf(e3*inv, fi[3].x, ax); ay = fmaf(e3*inv, fi[3].y, ay);
            az = fmaf(e3*inv, fi[3].z, az); aw = fmaf(e3*inv, fi[3].w, aw);
        }
        ull qa = pack2(ax, ay), qb = pack2(az, aw);
        qa = add2(qa, __shfl_xor_sync(0xffffffffu, qa, 16));
        qb = add2(qb, __shfl_xor_sync(0xffffffffu, qb, 16));
        unpack2(qa, ax, ay); unpack2(qb, az, aw);
        int vid = __shfl_sync(0xffffffffu, myv, e << 3);
        float4 vb = __ldcg(item4 + (size_t)vid*16 + c);
        ax += vb.x; ay += vb.y; az += vb.z; aw += vb.w;

        if (h == 0)
            *(float4*)(&sx[warp][EPW + e][4*c]) = make_float4(ax, ay, az, aw);
    }

    // pair barrier: both warps' staging visible before cross-warp matvec reads
    asm volatile("bar.sync %0, %1;" :: "r"(bar_id), "r"(64) : "memory");

    const int wE = pair << 1;            // even warp of this pair
    ull hh[8];
    if (!isodd){
        // even warp: Wu matvec over BOTH warps' user vectors (slots 0..3)
        matvec8((const ull*)Wu, (const ull*)bu,
                &sx[wE][0][0], &sx[wE+1][0][0], hh, lane);
        // store uh pairs into the (dead) user slots: e<4 -> sx[wE][e], else sx[wE+1][e-4]
        #pragma unroll
        for (int e = 0; e < 8; e++){
            float a, b; unpack2(hh[e], a, b);
            float* dst = (e < 4) ? &sx[wE][e][0] : &sx[wE+1][e-4][0];
            *(float2*)(dst + 2*lane) = make_float2(a, b);
        }
    } else {
        // odd warp: Wv matvec over BOTH warps' item vectors (slots 4..7)
        matvec8((const ull*)Wv, (const ull*)bv,
                &sx[wE][EPW][0], &sx[wE+1][EPW][0], hh, lane);
    }

    // pair barrier: uh stores visible to odd warp
    asm volatile("bar.sync %0, %1;" :: "r"(bar_id), "r"(64) : "memory");

    if (isodd){
        // score: sigmoid(dot(uh, vh)) * 5 for the pair's 8 elements
        float pe[8];
        #pragma unroll
        for (int e = 0; e < 8; e++){
            const float* src = (e < 4) ? &sx[wE][e][0] : &sx[wE+1][e-4][0];
            float2 uhp = *(const float2*)(src + 2*lane);
            float a, b; unpack2(hh[e], a, b);
            pe[e] = fmaf(uhp.x, a, uhp.y * b);
        }
        ull s0 = pack2(pe[0], pe[1]), s1 = pack2(pe[2], pe[3]);
        ull s2 = pack2(pe[4], pe[5]), s3 = pack2(pe[6], pe[7]);
        #pragma unroll
        for (int o = 16; o; o >>= 1){
            s0 = add2(s0, __shfl_xor_sync(0xffffffffu, s0, o));
            s1 = add2(s1, __shfl_xor_sync(0xffffffffu, s1, o));
            s2 = add2(s2, __shfl_xor_sync(0xffffffffu, s2, o));
            s3 = add2(s3, __shfl_xor_sync(0xffffffffu, s3, o));
        }
        if (lane == 0){
            const int pbase = (blockIdx.x * WPB + wE) * EPW;   // 8 consecutive elements
            float r[8];
            unpack2(s0, r[0], r[1]); unpack2(s1, r[2], r[3]);
            unpack2(s2, r[4], r[5]); unpack2(s3, r[6], r[7]);
            #pragma unroll
            for (int e = 0; e < 8; e++) r[e] = 5.f / (1.f + __expf(-r[e]));
            if (pbase + 8 <= batch){
                float4* o4 = (float4*)(out + pbase);
                o4[0] = make_float4(r[0], r[1], r[2], r[3]);
                o4[1] = make_float4(r[4], r[5], r[6], r[7]);
            } else {
                for (int e = 0; e < 8; e++)
                    if (pbase + e < batch) out[pbase + e] = r[e];
            }
        }
    }
}

extern "C" void kernel_launch(void* const* d_in, const int* in_sizes, int n_in,
                              void* d_out, int out_size)
{
    (void)n_in; (void)out_size;
    const int batch = in_sizes[0];
    const int blocks = (batch + WPB*EPW - 1) / (WPB*EPW);
    sestkgcn_kernel<<<blocks, NTHREADS>>>(
        (const int*)d_in[0],  (const int*)d_in[1],
        (const float*)d_in[2], (const float*)d_in[3], (const float*)d_in[4],
        (const int*)d_in[5],  (const float*)d_in[6],
        (const int*)d_in[7],  (const float*)d_in[8],  (const float*)d_in[9],  (const float*)d_in[10],
        (const int*)d_in[11], (const float*)d_in[12], (const float*)d_in[13], (const float*)d_in[14],
        (const int*)d_in[15], (const int*)d_in[16],
        (const float*)d_in[17], (const float*)d_in[18],
        (const float*)d_in[19], (const float*)d_in[20],
        (float*)d_out, batch);
}

// round 14
// speedup vs baseline: 1.0701x; 1.0701x over previous
#include <cuda_runtime.h>
#include <cstdint>

#define WPB 8          // warps per block
#define EPW 4          // elements per warp
#define NTHREADS 256
#define D 64
#define NS 8
#define NREL 64

typedef unsigned long long ull;

__device__ __forceinline__ ull pack2(float x, float y){
    ull r;
    asm("mov.b64 %0, {%1, %2};" : "=l"(r)
        : "r"(__float_as_uint(x)), "r"(__float_as_uint(y)));
    return r;
}
__device__ __forceinline__ void unpack2(ull p, float &x, float &y){
    unsigned int lo, hi;
    asm("mov.b64 {%0, %1}, %2;" : "=r"(lo), "=r"(hi) : "l"(p));
    x = __uint_as_float(lo); y = __uint_as_float(hi);
}
// packed fp32x2 ops (Blackwell)
__device__ __forceinline__ void ffma2(ull &acc, ull a, ull b){
    asm("fma.rn.f32x2 %0, %1, %2, %3;" : "=l"(acc) : "l"(a), "l"(b), "l"(acc));
}
__device__ __forceinline__ ull add2(ull a, ull b){
    ull r; asm("add.rn.f32x2 %0, %1, %2;" : "=l"(r) : "l"(a), "l"(b));
    return r;
}

// softmax over 8-lane group (lanes 8g..8g+7), one value per lane
__device__ __forceinline__ float gsoftmax8(float x){
    float m = x;
    m = fmaxf(m, __shfl_xor_sync(0xffffffffu, m, 1));
    m = fmaxf(m, __shfl_xor_sync(0xffffffffu, m, 2));
    m = fmaxf(m, __shfl_xor_sync(0xffffffffu, m, 4));
    float e = __expf(x - m);
    float sm = e;
    sm += __shfl_xor_sync(0xffffffffu, sm, 1);
    sm += __shfl_xor_sync(0xffffffffu, sm, 2);
    sm += __shfl_xor_sync(0xffffffffu, sm, 4);
    return e / sm;
}

// matvec: W from gmem (L1-resident; gathers bypass L1 via .cg),
// x from smem as PLAIN floats via LDS.128 (4 dims per wavefront);
// pair-duplication done with cheap ALU movs. Output pair per lane, relu'd.
__device__ __forceinline__ void matvec(const ull* __restrict__ Wg,
                                       const ull* __restrict__ bg,
                                       const float* __restrict__ sxe,
                                       ull* h, int lane){
    ull bias = bg[lane];
    ull acc[EPW];
    #pragma unroll
    for (int e = 0; e < EPW; e++) acc[e] = bias;
    #pragma unroll 4
    for (int dq = 0; dq < D/4; dq++){
        ull w0 = Wg[(4*dq)  * 32 + lane];   // (W[d][2l], W[d][2l+1])
        ull w1 = Wg[(4*dq+1)* 32 + lane];
        ull w2 = Wg[(4*dq+2)* 32 + lane];
        ull w3 = Wg[(4*dq+3)* 32 + lane];
        #pragma unroll
        for (int e = 0; e < EPW; e++){
            float4 x4 = *(const float4*)(sxe + e*D + 4*dq);  // 4 dims / 1 wavefront
            ffma2(acc[e], w0, pack2(x4.x, x4.x));
            ffma2(acc[e], w1, pack2(x4.y, x4.y));
            ffma2(acc[e], w2, pack2(x4.z, x4.z));
            ffma2(acc[e], w3, pack2(x4.w, x4.w));
        }
    }
    #pragma unroll
    for (int e = 0; e < EPW; e++){
        float a, b; unpack2(acc[e], a, b);
        h[e] = pack2(fmaxf(a, 0.f), fmaxf(b, 0.f));
    }
}

__global__ void __launch_bounds__(NTHREADS, 5)
sestkgcn_kernel(
    const int* __restrict__ u, const int* __restrict__ v,
    const float* __restrict__ usr_feat, const float* __restrict__ item_feat,
    const float* __restrict__ rel_feat,
    const int* __restrict__ neigh_uu, const float* __restrict__ uu_st,
    const int* __restrict__ neigh_ui, const float* __restrict__ ui_rat,
    const float* __restrict__ ui_vot, const float* __restrict__ ui_tim,
    const int* __restrict__ neigh_iu, const float* __restrict__ iu_rat,
    const float* __restrict__ iu_vot, const float* __restrict__ iu_tim,
    const int* __restrict__ neigh_ii, const int* __restrict__ neigh_ir,
    const float* __restrict__ Wu, const float* __restrict__ bu,
    const float* __restrict__ Wv, const float* __restrict__ bv,
    float* __restrict__ out, int batch)
{
    // plain x vectors, double-buffered (user slots 0..3, item 4..7): 16 KB
    __shared__ __align__(16) float sx[WPB][2*EPW][D];
    // relation table, resident in smem: 64 rows * 64 floats = 16 KB
    __shared__ __align__(16) float srel[NREL * D];

    const int warp = threadIdx.x >> 5;
    const int lane = threadIdx.x & 31;
    const int base = (blockIdx.x * WPB + warp) * EPW;

    // block-cooperative load of rel_feat into smem (coalesced float4)
    {
        const float4* rsrc = (const float4*)rel_feat;
        float4* rdst = (float4*)srel;
        #pragma unroll
        for (int i = threadIdx.x; i < (NREL * D) / 4; i += NTHREADS)
            rdst[i] = rsrc[i];
    }
    __syncthreads();

    const float4* usr4  = (const float4*)usr_feat;   // quarter base = id*16 + c
    const float4* item4 = (const float4*)item_feat;

    const int h = lane >> 4;   // row-of-pair selector
    const int c = lane & 15;   // float4 dim-quarter

    // ---------- lane-parallel weights & indices: lane = (e = lane>>3, s = lane&7) ----------
    const int eg = lane >> 3, sg = lane & 7;
    int bb = base + eg; if (bb >= batch) bb = batch - 1;
    const int myu = __ldcg(u + bb);
    const int myv = __ldcg(v + bb);

    float w_uu = __ldcg(uu_st + myu*NS + sg);
    int   i_uu = __ldcg(neigh_uu + myu*NS + sg);
    float w_ui = __ldcg(ui_rat + myu*NS + sg) * __ldcg(ui_vot + myu*NS + sg)
               * __ldcg(ui_tim + myu*NS + sg);
    int   i_ui = __ldcg(neigh_ui + myu*NS + sg);
    float w_iu = __ldcg(iu_rat + myv*NS + sg) * __ldcg(iu_vot + myv*NS + sg)
               * __ldcg(iu_tim + myv*NS + sg);
    int   i_iu = __ldcg(neigh_iu + myv*NS + sg);
    int   i_ii = __ldcg(neigh_ii + myv*NS + sg);
    int   i_ir = __ldcg(neigh_ir + myv*NS + sg);

    w_uu = gsoftmax8(w_uu);
    w_ui = gsoftmax8(w_ui);
    w_iu = gsoftmax8(w_iu);

    const ull p_uu = pack2(w_uu, __int_as_float(i_uu));
    const ull p_ui = pack2(w_ui, __int_as_float(i_ui));
    const ull p_iu = pack2(w_iu, __int_as_float(i_iu));
    const ull p_ii = pack2(__int_as_float(i_ii), __int_as_float(i_ir));

    // =============== user side: paired-row gathers (stage to slots 0..3) ===============
    #pragma unroll
    for (int e = 0; e < EPW; e++){
        float ax = 0.f, ay = 0.f, az = 0.f, aw = 0.f;

        // social neighbors: 4 pair-steps, lane half h takes row 2s+h
        #pragma unroll
        for (int s = 0; s < 4; s++){
            ull t = __shfl_sync(0xffffffffu, p_uu, (e << 3) + 2*s + h);
            float wf, idf; unpack2(t, wf, idf);
            float4 f = __ldcg(usr4 + (size_t)__float_as_int(idf)*16 + c);
            ax = fmaf(wf, f.x, ax); ay = fmaf(wf, f.y, ay);
            az = fmaf(wf, f.z, az); aw = fmaf(wf, f.w, aw);
        }
        // interacted items
        #pragma unroll
        for (int s = 0; s < 4; s++){
            ull t = __shfl_sync(0xffffffffu, p_ui, (e << 3) + 2*s + h);
            float wf, idf; unpack2(t, wf, idf);
            float4 f = __ldcg(item4 + (size_t)__float_as_int(idf)*16 + c);
            ax = fmaf(wf, f.x, ax); ay = fmaf(wf, f.y, ay);
            az = fmaf(wf, f.z, az); aw = fmaf(wf, f.w, aw);
        }
        // combine row-halves
        ull qa = pack2(ax, ay), qb = pack2(az, aw);
        qa = add2(qa, __shfl_xor_sync(0xffffffffu, qa, 16));
        qb = add2(qb, __shfl_xor_sync(0xffffffffu, qb, 16));
        unpack2(qa, ax, ay); unpack2(qb, az, aw);
        // add base u embedding (L1-cached: re-read in KG phase hits L1)
        int uid = __shfl_sync(0xffffffffu, myu, e << 3);
        float4 ub = __ldg(usr4 + (size_t)uid*16 + c);
        ax += ub.x; ay += ub.y; az += ub.z; aw += ub.w;

        if (h == 0)
            *(float4*)(&sx[warp][e][4*c]) = make_float4(ax, ay, az, aw);
    }

    // =============== item side: paired-row gathers (stage to slots 4..7) ===============
    #pragma unroll
    for (int e = 0; e < EPW; e++){
        float ax = 0.f, ay = 0.f, az = 0.f, aw = 0.f;

        // interacting users
        #pragma unroll
        for (int s = 0; s < 4; s++){
            ull t = __shfl_sync(0xffffffffu, p_iu, (e << 3) + 2*s + h);
            float wf, idf; unpack2(t, wf, idf);
            float4 f = __ldcg(usr4 + (size_t)__float_as_int(idf)*16 + c);
            ax = fmaf(wf, f.x, ax); ay = fmaf(wf, f.y, ay);
            az = fmaf(wf, f.z, az); aw = fmaf(wf, f.w, aw);
        }
        // KG neighbors with user-relation attention (rel rows from SMEM, 16-lane reduce)
        {
            int uid = __shfl_sync(0xffffffffu, myu, e << 3);
            float4 ue = __ldg(usr4 + (size_t)uid*16 + c);   // L1 hit (cached above)

            int iidx[4]; float4 fi[4]; float ps[4];
            #pragma unroll
            for (int s = 0; s < 4; s++){
                ull t = __shfl_sync(0xffffffffu, p_ii, (e << 3) + 2*s + h);
                float af, bf; unpack2(t, af, bf);
                iidx[s] = __float_as_int(af);
                fi[s] = __ldcg(item4 + (size_t)iidx[s]*16 + c);
                float4 rf = *(const float4*)(srel + __float_as_int(bf)*D + 4*c); // 29-cyc LDS
                ps[s] = fmaf(ue.x, rf.x, fmaf(ue.y, rf.y, fmaf(ue.z, rf.z, ue.w * rf.w)));
            }
            // butterfly over 16-lane halves: lanes of half h end with dots of rows 2s+h
            ull q0 = pack2(ps[0], ps[1]), q1 = pack2(ps[2], ps[3]);
            #pragma unroll
            for (int o = 8; o; o >>= 1){
                q0 = add2(q0, __shfl_xor_sync(0xffffffffu, q0, o));
                q1 = add2(q1, __shfl_xor_sync(0xffffffffu, q1, o));
            }
            // fetch other half's 4 dots for normalization
            ull q0o = __shfl_xor_sync(0xffffffffu, q0, 16);
            ull q1o = __shfl_xor_sync(0xffffffffu, q1, 16);
            float d0,d1,d2,d3, o0,o1,o2,o3;
            unpack2(q0, d0, d1); unpack2(q1, d2, d3);
            unpack2(q0o, o0, o1); unpack2(q1o, o2, o3);
            float m = fmaxf(fmaxf(fmaxf(d0,d1), fmaxf(d2,d3)),
                            fmaxf(fmaxf(o0,o1), fmaxf(o2,o3)));
            float e0 = __expf(d0-m), e1 = __expf(d1-m), e2 = __expf(d2-m), e3 = __expf(d3-m);
            float sum = e0+e1+e2+e3 + __expf(o0-m)+__expf(o1-m)+__expf(o2-m)+__expf(o3-m);
            float inv = 1.f / sum;
            ax = fmaf(e0*inv, fi[0].x, ax); ay = fmaf(e0*inv, fi[0].y, ay);
            az = fmaf(e0*inv, fi[0].z, az); aw = fmaf(e0*inv, fi[0].w, aw);
            ax = fmaf(e1*inv, fi[1].x, ax); ay = fmaf(e1*inv, fi[1].y, ay);
            az = fmaf(e1*inv, fi[1].z, az); aw = fmaf(e1*inv, fi[1].w, aw);
            ax = fmaf(e2*inv, fi[2].x, ax); ay = fmaf(e2*inv, fi[2].y, ay);
            az = fmaf(e2*inv, fi[2].z, az); aw = fmaf(e2*inv, fi[2].w, aw);
            ax = fmaf(e3*inv, fi[3].x, ax); ay = fmaf(e3*inv, fi[3].y, ay);
            az = fmaf(e3*inv, fi[3].z, az); aw = fmaf(e3*inv, fi[3].w, aw);
        }
        // combine row-halves
        ull qa = pack2(ax, ay), qb = pack2(az, aw);
        qa = add2(qa, __shfl_xor_sync(0xffffffffu, qa, 16));
        qb = add2(qb, __shfl_xor_sync(0xffffffffu, qb, 16));
        unpack2(qa, ax, ay); unpack2(qb, az, aw);
        // add base v embedding
        int vid = __shfl_sync(0xffffffffu, myv, e << 3);
        float4 vb = __ldcg(item4 + (size_t)vid*16 + c);
        ax += vb.x; ay += vb.y; az += vb.z; aw += vb.w;

        if (h == 0)
            *(float4*)(&sx[warp][EPW + e][4*c]) = make_float4(ax, ay, az, aw);
    }
    __syncwarp();   // staging visible; both matvecs follow back-to-back

    // =============== both matvecs (independent; W loads overlap) ===============
    ull uh[EPW], vh[EPW];
    matvec((const ull*)Wu, (const ull*)bu, &sx[warp][0][0],   uh, lane);
    matvec((const ull*)Wv, (const ull*)bv, &sx[warp][EPW][0], vh, lane);

    // =============== score: sigmoid(dot(user_h, item_h)) * 5 ===============
    float pe[EPW];
    #pragma unroll
    for (int e = 0; e < EPW; e++){
        float a0, a1, b0, b1;
        unpack2(uh[e], a0, a1);
        unpack2(vh[e], b0, b1);
        pe[e] = fmaf(a0, b0, a1 * b1);
    }
    ull s01 = pack2(pe[0], pe[1]), s23 = pack2(pe[2], pe[3]);
    #pragma unroll
    for (int o = 16; o; o >>= 1){
        s01 = add2(s01, __shfl_xor_sync(0xffffffffu, s01, o));
        s23 = add2(s23, __shfl_xor_sync(0xffffffffu, s23, o));
    }
    if (lane == 0){
        float r[EPW];
        unpack2(s01, r[0], r[1]);
        unpack2(s23, r[2], r[3]);
        #pragma unroll
        for (int e = 0; e < EPW; e++) r[e] = 5.f / (1.f + __expf(-r[e]));
        if (base + EPW <= batch){
            *(float4*)(out + base) = make_float4(r[0], r[1], r[2], r[3]);
        } else {
            for (int e = 0; e < EPW; e++)
                if (base + e < batch) out[base + e] = r[e];
        }
    }
}

extern "C" void kernel_launch(void* const* d_in, const int* in_sizes, int n_in,
                              void* d_out, int out_size)
{
    (void)n_in; (void)out_size;
    const int batch = in_sizes[0];
    const int blocks = (batch + WPB*EPW - 1) / (WPB*EPW);
    sestkgcn_kernel<<<blocks, NTHREADS>>>(
        (const int*)d_in[0],  (const int*)d_in[1],
        (const float*)d_in[2], (const float*)d_in[3], (const float*)d_in[4],
        (const int*)d_in[5],  (const float*)d_in[6],
        (const int*)d_in[7],  (const float*)d_in[8],  (const float*)d_in[9],  (const float*)d_in[10],
        (const int*)d_in[11], (const float*)d_in[12], (const float*)d_in[13], (const float*)d_in[14],
        (const int*)d_in[15], (const int*)d_in[16],
        (const float*)d_in[17], (const float*)d_in[18],
        (const float*)d_in[19], (const float*)d_in[20],
        (float*)d_out, batch);
}